// round 2
// baseline (speedup 1.0000x reference)
#include <cuda_runtime.h>
#include <cstdint>

// Problem constants (deterministic per setup_inputs)
#define BATCH   4096
#define IDIM    1024
#define LDIM    1024
#define HDIM    2048
#define ODIM    512
#define HALTH   1024
#define OUTER   8
#define INNER   4

// ---------------------------------------------------------------------------
// Scratch (device globals; no allocation allowed)
// ---------------------------------------------------------------------------
__device__ float g_state[BATCH * LDIM];      // 16 MB
__device__ float g_ans[BATCH * ODIM];        // 8 MB
__device__ float g_xg[BATCH * 3 * LDIM];     // 48 MB
__device__ float g_hg[BATCH * 3 * LDIM];     // 48 MB
__device__ float g_h1[BATCH * HDIM];         // 32 MB
__device__ float g_h2[BATCH * HALTH];        // 16 MB

__device__ __forceinline__ uint32_t f2tf32(float x) {
    uint32_t r;
    asm("cvt.rna.tf32.f32 %0, %1;" : "=r"(r) : "f"(x));
    return r;
}

#define EPI_NONE   0
#define EPI_RELU   1
#define EPI_LOGITS 2

#define SSTRIDE 20   // floats per smem row (16 data + 4 pad) -> conflict-free

// ---------------------------------------------------------------------------
// tf32 mma.sync GEMM with 2-stage cp.async pipeline:
//   C[M,N] = epi( A @ W^T + bias )
//   A: [M,K] row-major, logically concat(A1[:, :K1], A2[:, K1:]) along K
//   W: [N,K] row-major
//   BM=BN=128, BK=16, 256 threads (8 warps, 4x2), warp tile 32x64
// ---------------------------------------------------------------------------
template <int EPI>
__global__ void __launch_bounds__(256, 2)
gemm_tf32(const float* __restrict__ A1, int lda1, int K1,
          const float* __restrict__ A2, int lda2,
          const float* __restrict__ W,
          const float* __restrict__ bias,
          float* __restrict__ C,
          float* __restrict__ C2,   // secondary output (tanh(logits) -> ans)
          int N, int K)
{
    // [stage][A=0/B=1][128 rows * SSTRIDE]   = 2*2*10240 B * ... = 40960 B
    __shared__ float smem[2][2][128 * SSTRIDE];

    const int tid  = threadIdx.x;
    const int lane = tid & 31;
    const int warp = tid >> 5;
    const int wm   = warp >> 1;  // 0..3
    const int wn   = warp & 1;   // 0..1
    const int row0 = blockIdx.y * 128;
    const int col0 = blockIdx.x * 128;

    float c[2][8][4];
#pragma unroll
    for (int i = 0; i < 2; i++)
#pragma unroll
        for (int j = 0; j < 8; j++)
#pragma unroll
            for (int k = 0; k < 4; k++) c[i][j][k] = 0.0f;

    // Loader mapping: 512 16B-chunks per matrix tile -> 2 per thread.
    // idx = tid*2 + j ; r = idx>>2 (0..127) ; c4 = (idx&3)*4 (float col)
    const int ntiles = K >> 4;

    auto issue_tile = [&](int t) {
        const int k0 = t << 4;
        const float* Ab;
        int lda;
        if (k0 < K1) { Ab = A1 + k0;        lda = lda1; }
        else         { Ab = A2 + (k0 - K1); lda = lda2; }
        float* dA = smem[t & 1][0];
        float* dB = smem[t & 1][1];
#pragma unroll
        for (int j = 0; j < 2; j++) {
            const int idx = tid * 2 + j;
            const int r   = idx >> 2;
            const int c4  = (idx & 3) * 4;
            uint32_t da = (uint32_t)__cvta_generic_to_shared(dA + r * SSTRIDE + c4);
            const float* ga = Ab + (size_t)(row0 + r) * lda + c4;
            asm volatile("cp.async.cg.shared.global [%0], [%1], 16;\n"
                         :: "r"(da), "l"(ga));
            uint32_t db = (uint32_t)__cvta_generic_to_shared(dB + r * SSTRIDE + c4);
            const float* gb = W + (size_t)(col0 + r) * K + k0 + c4;
            asm volatile("cp.async.cg.shared.global [%0], [%1], 16;\n"
                         :: "r"(db), "l"(gb));
        }
        asm volatile("cp.async.commit_group;\n");
    };

    issue_tile(0);

    for (int t = 0; t < ntiles; t++) {
        asm volatile("cp.async.wait_group 0;\n");
        __syncthreads();                 // tile t visible; all compute t-1 done
        if (t + 1 < ntiles) issue_tile(t + 1);   // overlaps with compute below

        const float* sA = smem[t & 1][0];
        const float* sB = smem[t & 1][1];

#pragma unroll
        for (int ks = 0; ks < 16; ks += 8) {
            uint32_t a[2][4], b[8][2];
#pragma unroll
            for (int mi = 0; mi < 2; mi++) {
                const int r  = wm * 32 + mi * 16 + (lane >> 2);
                const int cc = ks + (lane & 3);
                a[mi][0] = f2tf32(sA[r * SSTRIDE + cc]);
                a[mi][1] = f2tf32(sA[(r + 8) * SSTRIDE + cc]);
                a[mi][2] = f2tf32(sA[r * SSTRIDE + cc + 4]);
                a[mi][3] = f2tf32(sA[(r + 8) * SSTRIDE + cc + 4]);
            }
#pragma unroll
            for (int ni = 0; ni < 8; ni++) {
                const int n  = wn * 64 + ni * 8 + (lane >> 2);
                const int kk = ks + (lane & 3);
                b[ni][0] = f2tf32(sB[n * SSTRIDE + kk]);
                b[ni][1] = f2tf32(sB[n * SSTRIDE + kk + 4]);
            }
#pragma unroll
            for (int mi = 0; mi < 2; mi++)
#pragma unroll
                for (int ni = 0; ni < 8; ni++) {
                    asm volatile(
                        "mma.sync.aligned.m16n8k8.row.col.f32.tf32.tf32.f32 "
                        "{%0,%1,%2,%3},{%4,%5,%6,%7},{%8,%9},{%0,%1,%2,%3};\n"
                        : "+f"(c[mi][ni][0]), "+f"(c[mi][ni][1]),
                          "+f"(c[mi][ni][2]), "+f"(c[mi][ni][3])
                        : "r"(a[mi][0]), "r"(a[mi][1]), "r"(a[mi][2]), "r"(a[mi][3]),
                          "r"(b[ni][0]), "r"(b[ni][1]));
                }
        }
        // no trailing sync: next iter's top sync protects the buffer reuse
    }

    // Epilogue
#pragma unroll
    for (int mi = 0; mi < 2; mi++) {
        const int rbase = row0 + wm * 32 + mi * 16 + (lane >> 2);
#pragma unroll
        for (int ni = 0; ni < 8; ni++) {
            const int col = col0 + wn * 64 + ni * 8 + (lane & 3) * 2;
            const float b0 = bias[col];
            const float b1 = bias[col + 1];
            float v00 = c[mi][ni][0] + b0;
            float v01 = c[mi][ni][1] + b1;
            float v10 = c[mi][ni][2] + b0;
            float v11 = c[mi][ni][3] + b1;
            if (EPI == EPI_RELU) {
                v00 = fmaxf(v00, 0.0f); v01 = fmaxf(v01, 0.0f);
                v10 = fmaxf(v10, 0.0f); v11 = fmaxf(v11, 0.0f);
            }
            const size_t i0 = (size_t)rbase * N + col;
            const size_t i1 = (size_t)(rbase + 8) * N + col;
            C[i0] = v00; C[i0 + 1] = v01;
            C[i1] = v10; C[i1 + 1] = v11;
            if (EPI == EPI_LOGITS) {
                C2[i0] = tanhf(v00); C2[i0 + 1] = tanhf(v01);
                C2[i1] = tanhf(v10); C2[i1 + 1] = tanhf(v11);
            }
        }
    }
}

// ---------------------------------------------------------------------------
// GRU elementwise: state = (1-z)*n + z*state  (PyTorch GRUCell gate order r,z,n)
// ---------------------------------------------------------------------------
__global__ void gru_kernel()
{
    const int idx = blockIdx.x * blockDim.x + threadIdx.x;  // BATCH*LDIM threads
    const int row = idx >> 10;        // LDIM = 1024
    const int j   = idx & 1023;
    const float* xg = g_xg + (size_t)row * (3 * LDIM);
    const float* hg = g_hg + (size_t)row * (3 * LDIM);
    const float xr = xg[j], xz = xg[LDIM + j], xn = xg[2 * LDIM + j];
    const float hr = hg[j], hz = hg[LDIM + j], hn = hg[2 * LDIM + j];
    const float s = g_state[idx];
    const float r = 1.0f / (1.0f + expf(-(xr + hr)));
    const float z = 1.0f / (1.0f + expf(-(xz + hz)));
    const float n = tanhf(xn + r * hn);
    g_state[idx] = (1.0f - z) * n + z * s;
}

// ---------------------------------------------------------------------------
// Halt head: halt[b, 0:2] = h2[b,:] @ hw2[0:2,:]^T + hb2 ; warp per row
// ---------------------------------------------------------------------------
__global__ void halt_kernel(const float* __restrict__ hw2,
                            const float* __restrict__ hb2,
                            float* __restrict__ out)
{
    const int row  = blockIdx.x * (blockDim.x >> 5) + (threadIdx.x >> 5);
    const int lane = threadIdx.x & 31;
    const float* h = g_h2 + (size_t)row * HALTH;
    float s0 = 0.0f, s1 = 0.0f;
    for (int k = lane; k < HALTH; k += 32) {
        const float v = h[k];
        s0 += v * hw2[k];
        s1 += v * hw2[HALTH + k];
    }
#pragma unroll
    for (int o = 16; o > 0; o >>= 1) {
        s0 += __shfl_down_sync(0xFFFFFFFFu, s0, o);
        s1 += __shfl_down_sync(0xFFFFFFFFu, s1, o);
    }
    if (lane == 0) {
        out[(size_t)row * 2]     = s0 + hb2[0];
        out[(size_t)row * 2 + 1] = s1 + hb2[1];
    }
}

// ---------------------------------------------------------------------------
// Host orchestration
// ---------------------------------------------------------------------------
extern "C" void kernel_launch(void* const* d_in, const int* in_sizes, int n_in,
                              void* d_out, int out_size)
{
    const float* inputs = (const float*)d_in[0];
    const float* W_ih   = (const float*)d_in[1];
    const float* W_hh   = (const float*)d_in[2];
    const float* b_ih   = (const float*)d_in[3];
    const float* b_hh   = (const float*)d_in[4];
    const float* aw1    = (const float*)d_in[5];
    const float* ab1    = (const float*)d_in[6];
    const float* aw2    = (const float*)d_in[7];
    const float* ab2    = (const float*)d_in[8];
    const float* hw1    = (const float*)d_in[9];
    const float* hb1    = (const float*)d_in[10];
    const float* hw2    = (const float*)d_in[11];
    const float* hb2    = (const float*)d_in[12];
    // d_in[13]=inner_cycles(4), d_in[14]=outer_steps(8): fixed by setup_inputs.

    float* out = (float*)d_out;
    float* ans_out  = out;                                    // [8, 4096, 512]
    float* halt_out = out + (size_t)OUTER * BATCH * ODIM;     // [8, 4096, 2]

    float *pstate, *pans, *pxg, *phg, *ph1, *ph2;
    cudaGetSymbolAddress((void**)&pstate, g_state);
    cudaGetSymbolAddress((void**)&pans,   g_ans);
    cudaGetSymbolAddress((void**)&pxg,    g_xg);
    cudaGetSymbolAddress((void**)&phg,    g_hg);
    cudaGetSymbolAddress((void**)&ph1,    g_h1);
    cudaGetSymbolAddress((void**)&ph2,    g_h2);

    cudaMemsetAsync(pstate, 0, sizeof(float) * BATCH * LDIM);
    cudaMemsetAsync(pans,   0, sizeof(float) * BATCH * ODIM);

    const dim3 blk(256);
    const int MR = BATCH / 128;  // 32 row blocks

    for (int s = 0; s < OUTER; s++) {
        // x_gates = concat(inputs, ans) @ W_ih^T + b_ih     [B, 3L]
        gemm_tf32<EPI_NONE><<<dim3((3 * LDIM) / 128, MR), blk>>>(
            inputs, IDIM, IDIM, pans, ODIM, W_ih, b_ih,
            pxg, nullptr, 3 * LDIM, IDIM + ODIM);

        for (int i = 0; i < INNER; i++) {
            // h_gates = state @ W_hh^T + b_hh               [B, 3L]
            gemm_tf32<EPI_NONE><<<dim3((3 * LDIM) / 128, MR), blk>>>(
                pstate, LDIM, LDIM, pstate, LDIM, W_hh, b_hh,
                phg, nullptr, 3 * LDIM, LDIM);
            gru_kernel<<<(BATCH * LDIM) / 256, 256>>>();
        }

        // h1 = relu(concat(state, ans) @ aw1^T + ab1)       [B, H]
        gemm_tf32<EPI_RELU><<<dim3(HDIM / 128, MR), blk>>>(
            pstate, LDIM, LDIM, pans, ODIM, aw1, ab1,
            ph1, nullptr, HDIM, LDIM + ODIM);

        // h2 = relu(concat(state, ans) @ hw1^T + hb1)       [B, HALT_H]
        gemm_tf32<EPI_RELU><<<dim3(HALTH / 128, MR), blk>>>(
            pstate, LDIM, LDIM, pans, ODIM, hw1, hb1,
            ph2, nullptr, HALTH, LDIM + ODIM);

        // halt = h2 @ hw2^T + hb2                           [B, 2]
        halt_kernel<<<BATCH / 8, 256>>>(hw2, hb2, halt_out + (size_t)s * BATCH * 2);

        // logits = h1 @ aw2^T + ab2 -> out; ans = tanh(logits)   (LAST: overwrites ans)
        gemm_tf32<EPI_LOGITS><<<dim3(ODIM / 128, MR), blk>>>(
            ph1, HDIM, HDIM, ph1, HDIM, aw2, ab2,
            ans_out + (size_t)s * BATCH * ODIM, pans, ODIM, HDIM);
    }
}

// round 4
// speedup vs baseline: 2.5363x; 2.5363x over previous
#include <cuda_runtime.h>
#include <cuda_fp16.h>
#include <cstdint>
#include <math.h>

#define BATCH   4096
#define IDIM    1024
#define LDIM    1024
#define HDIM    2048
#define ODIM    512
#define HALTH   1024
#define OUTER   8
#define INNER   4

// ---------------------------------------------------------------------------
// Device-global scratch (no allocation allowed)
// ---------------------------------------------------------------------------
__device__ float  g_state[BATCH * LDIM];
__device__ float  g_xg[BATCH * 3 * LDIM];
__device__ float  g_hg[BATCH * 3 * LDIM];
__device__ float  g_h2[BATCH * HALTH];

__device__ __half g_state16[BATCH * LDIM];
__device__ __half g_ans16[BATCH * ODIM];
__device__ __half g_in16[BATCH * IDIM];
__device__ __half g_h116[BATCH * HDIM];

__device__ __half g_wih16[3 * LDIM * (IDIM + ODIM)];
__device__ __half g_whh16[3 * LDIM * LDIM];
__device__ __half g_aw116[HDIM * (LDIM + ODIM)];
__device__ __half g_aw216[ODIM * HDIM];
__device__ __half g_hw116[HALTH * (LDIM + ODIM)];

__device__ __forceinline__ uint32_t smem_u32(const void* p) {
    uint32_t a;
    asm("{ .reg .u64 t; cvta.to.shared.u64 t, %1; cvt.u32.u64 %0, t; }" : "=r"(a) : "l"(p));
    return a;
}

// Swizzled smem layout for a 128-row x 32-half (64B) tile packed as 128B lines:
// 16B-unit offset for (row r, 16B-chunk c in 0..3). Conflict-free for ldmatrix
// (8 consecutive rows at fixed c hit 8 distinct 16B banks) and for cp.async fill.
__device__ __forceinline__ uint32_t soff(int r, int c) {
    return (uint32_t)((((r >> 1) * 8) + ((((r & 1) << 2) | c) ^ ((r >> 1) & 7))) << 4);
}

// ---------------------------------------------------------------------------
// fp16 tensor-core GEMM:  C[M,N] = act( A @ W^T + bias )
//   A: [M,K] fp16 row-major = concat(A1[:, :K1], A2[:, K1:]) (K1 % 32 == 0)
//   W: [N,K] fp16 row-major
//   BM=BN=128, BK=32, 256 threads (8 warps 4x2), warp tile 32x64
//   3-stage cp.async pipeline, ldmatrix.x4 fragments, mma.m16n8k16
//   WRITE32 -> C (fp32), WRITE16 -> C2 (fp16). ACT: 0 none, 1 relu,
//   2 logits (C = raw fp32, C2 = half(tanh))
// ---------------------------------------------------------------------------
template <int WRITE32, int WRITE16, int ACT>
__global__ void __launch_bounds__(256)
hgemm(const __half* __restrict__ A1, int lda1, int K1,
      const __half* __restrict__ A2, int lda2,
      const __half* __restrict__ W,
      const float* __restrict__ bias,
      float* __restrict__ C,
      __half* __restrict__ C2,
      int N, int K)
{
    __shared__ __align__(128) char smem[3 * 16384];   // 3 stages x (8KB A + 8KB B)
    const uint32_t sb = smem_u32(smem);

    const int tid  = threadIdx.x;
    const int lane = tid & 31;
    const int warp = tid >> 5;
    const int wm   = warp >> 1;    // 0..3
    const int wn   = warp & 1;     // 0..1
    const int row0 = blockIdx.y * 128;
    const int col0 = blockIdx.x * 128;

    float c[2][8][4];
#pragma unroll
    for (int i = 0; i < 2; i++)
#pragma unroll
        for (int j = 0; j < 8; j++)
#pragma unroll
            for (int k = 0; k < 4; k++) c[i][j][k] = 0.0f;

    const int nc = K >> 5;

    auto load_chunk = [&](int t) {
        const int st = t % 3;
        const int k0 = t << 5;
        const __half* Ab;
        int lda;
        if (k0 < K1) { Ab = A1 + k0;        lda = lda1; }
        else         { Ab = A2 + (k0 - K1); lda = lda2; }
        const uint32_t aB = sb + st * 16384;
        const uint32_t bB = aB + 8192;
#pragma unroll
        for (int j = 0; j < 2; j++) {
            const int idx = j * 256 + tid;
            const int r = idx >> 2, cc = idx & 3;
            const uint32_t da = aB + soff(r, cc);
            const __half* ga = Ab + (size_t)(row0 + r) * lda + cc * 8;
            asm volatile("cp.async.cg.shared.global [%0], [%1], 16;" :: "r"(da), "l"(ga));
            const uint32_t db = bB + soff(r, cc);
            const __half* gb = W + (size_t)(col0 + r) * K + k0 + cc * 8;
            asm volatile("cp.async.cg.shared.global [%0], [%1], 16;" :: "r"(db), "l"(gb));
        }
        asm volatile("cp.async.commit_group;");
    };

    load_chunk(0);
    load_chunk(1);

    for (int t = 0; t < nc; t++) {
        if (t + 2 <= nc) asm volatile("cp.async.wait_group 1;");
        else             asm volatile("cp.async.wait_group 0;");
        __syncthreads();
        if (t + 2 < nc) load_chunk(t + 2);

        const uint32_t aB = sb + (t % 3) * 16384;
        const uint32_t bB = aB + 8192;

#pragma unroll
        for (int kh = 0; kh < 2; kh++) {
            uint32_t a[2][4];
#pragma unroll
            for (int mi = 0; mi < 2; mi++) {
                const int row = wm * 32 + mi * 16 + (lane & 15);
                const int cc  = kh * 2 + (lane >> 4);
                const uint32_t ad = aB + soff(row, cc);
                asm volatile("ldmatrix.sync.aligned.m8n8.x4.shared.b16 {%0,%1,%2,%3}, [%4];"
                             : "=r"(a[mi][0]), "=r"(a[mi][1]), "=r"(a[mi][2]), "=r"(a[mi][3])
                             : "r"(ad));
            }
            uint32_t b[4][4];
#pragma unroll
            for (int ng = 0; ng < 4; ng++) {
                const int row = wn * 64 + ng * 16 + (lane & 7) + ((lane >> 4) << 3);
                const int cc  = kh * 2 + ((lane >> 3) & 1);
                const uint32_t bd = bB + soff(row, cc);
                asm volatile("ldmatrix.sync.aligned.m8n8.x4.shared.b16 {%0,%1,%2,%3}, [%4];"
                             : "=r"(b[ng][0]), "=r"(b[ng][1]), "=r"(b[ng][2]), "=r"(b[ng][3])
                             : "r"(bd));
            }
#pragma unroll
            for (int mi = 0; mi < 2; mi++)
#pragma unroll
                for (int ng = 0; ng < 4; ng++) {
                    asm volatile(
                        "mma.sync.aligned.m16n8k16.row.col.f32.f16.f16.f32 "
                        "{%0,%1,%2,%3},{%4,%5,%6,%7},{%8,%9},{%0,%1,%2,%3};"
                        : "+f"(c[mi][2 * ng][0]), "+f"(c[mi][2 * ng][1]),
                          "+f"(c[mi][2 * ng][2]), "+f"(c[mi][2 * ng][3])
                        : "r"(a[mi][0]), "r"(a[mi][1]), "r"(a[mi][2]), "r"(a[mi][3]),
                          "r"(b[ng][0]), "r"(b[ng][1]));
                    asm volatile(
                        "mma.sync.aligned.m16n8k16.row.col.f32.f16.f16.f32 "
                        "{%0,%1,%2,%3},{%4,%5,%6,%7},{%8,%9},{%0,%1,%2,%3};"
                        : "+f"(c[mi][2 * ng + 1][0]), "+f"(c[mi][2 * ng + 1][1]),
                          "+f"(c[mi][2 * ng + 1][2]), "+f"(c[mi][2 * ng + 1][3])
                        : "r"(a[mi][0]), "r"(a[mi][1]), "r"(a[mi][2]), "r"(a[mi][3]),
                          "r"(b[ng][2]), "r"(b[ng][3]));
                }
        }
    }

    // Epilogue (direct stores; c-frag: rows lane>>2 / +8, cols (lane&3)*2)
#pragma unroll
    for (int mi = 0; mi < 2; mi++) {
        const int r0 = row0 + wm * 32 + mi * 16 + (lane >> 2);
#pragma unroll
        for (int ni = 0; ni < 8; ni++) {
            const int col = col0 + wn * 64 + ni * 8 + (lane & 3) * 2;
            const float b0 = __ldg(&bias[col]);
            const float b1 = __ldg(&bias[col + 1]);
            float v00 = c[mi][ni][0] + b0;
            float v01 = c[mi][ni][1] + b1;
            float v10 = c[mi][ni][2] + b0;
            float v11 = c[mi][ni][3] + b1;
            if (ACT == 1) {
                v00 = fmaxf(v00, 0.0f); v01 = fmaxf(v01, 0.0f);
                v10 = fmaxf(v10, 0.0f); v11 = fmaxf(v11, 0.0f);
            }
            const size_t i0 = (size_t)r0 * N + col;
            const size_t i1 = (size_t)(r0 + 8) * N + col;
            if (WRITE32) {
                C[i0] = v00; C[i0 + 1] = v01;
                C[i1] = v10; C[i1 + 1] = v11;
            }
            if (WRITE16) {
                float w00 = v00, w01 = v01, w10 = v10, w11 = v11;
                if (ACT == 2) {
                    w00 = tanhf(v00); w01 = tanhf(v01);
                    w10 = tanhf(v10); w11 = tanhf(v11);
                }
                *(__half2*)&C2[i0] = __floats2half2_rn(w00, w01);
                *(__half2*)&C2[i1] = __floats2half2_rn(w10, w11);
            }
        }
    }
}

// ---------------------------------------------------------------------------
// Elementwise / small kernels
// ---------------------------------------------------------------------------
__global__ void cvt16(const float* __restrict__ src, __half* __restrict__ dst) {
    const int i = blockIdx.x * blockDim.x + threadIdx.x;
    dst[i] = __float2half_rn(src[i]);
}

__global__ void gru_kernel() {
    const int idx = blockIdx.x * blockDim.x + threadIdx.x;  // BATCH*LDIM
    const int row = idx >> 10;
    const int j   = idx & 1023;
    const float* xg = g_xg + (size_t)row * (3 * LDIM);
    const float* hg = g_hg + (size_t)row * (3 * LDIM);
    const float xr = xg[j], xz = xg[LDIM + j], xn = xg[2 * LDIM + j];
    const float hr = hg[j], hz = hg[LDIM + j], hn = hg[2 * LDIM + j];
    const float s = g_state[idx];
    const float r = 1.0f / (1.0f + expf(-(xr + hr)));
    const float z = 1.0f / (1.0f + expf(-(xz + hz)));
    const float n = tanhf(xn + r * hn);
    const float ns = (1.0f - z) * n + z * s;
    g_state[idx]   = ns;
    g_state16[idx] = __float2half_rn(ns);
}

__global__ void halt_kernel(const float* __restrict__ hw2,
                            const float* __restrict__ hb2,
                            float* __restrict__ out) {
    const int row  = blockIdx.x * (blockDim.x >> 5) + (threadIdx.x >> 5);
    const int lane = threadIdx.x & 31;
    const float* h = g_h2 + (size_t)row * HALTH;
    float s0 = 0.0f, s1 = 0.0f;
    for (int k = lane; k < HALTH; k += 32) {
        const float v = h[k];
        s0 += v * hw2[k];
        s1 += v * hw2[HALTH + k];
    }
#pragma unroll
    for (int o = 16; o > 0; o >>= 1) {
        s0 += __shfl_down_sync(0xFFFFFFFFu, s0, o);
        s1 += __shfl_down_sync(0xFFFFFFFFu, s1, o);
    }
    if (lane == 0) {
        out[(size_t)row * 2]     = s0 + hb2[0];
        out[(size_t)row * 2 + 1] = s1 + hb2[1];
    }
}

// ---------------------------------------------------------------------------
// Host orchestration
// ---------------------------------------------------------------------------
extern "C" void kernel_launch(void* const* d_in, const int* in_sizes, int n_in,
                              void* d_out, int out_size)
{
    const float* inputs = (const float*)d_in[0];
    const float* W_ih   = (const float*)d_in[1];
    const float* W_hh   = (const float*)d_in[2];
    const float* b_ih   = (const float*)d_in[3];
    const float* b_hh   = (const float*)d_in[4];
    const float* aw1    = (const float*)d_in[5];
    const float* ab1    = (const float*)d_in[6];
    const float* aw2    = (const float*)d_in[7];
    const float* ab2    = (const float*)d_in[8];
    const float* hw1    = (const float*)d_in[9];
    const float* hb1    = (const float*)d_in[10];
    const float* hw2    = (const float*)d_in[11];
    const float* hb2    = (const float*)d_in[12];

    float* out = (float*)d_out;
    float* ans_out  = out;                                  // [8, 4096, 512]
    float* halt_out = out + (size_t)OUTER * BATCH * ODIM;   // [8, 4096, 2]

    float *pstate, *pxg, *phg, *ph2;
    __half *pstate16, *pans16, *pin16, *ph116;
    __half *pwih, *pwhh, *paw1, *paw2, *phw1;
    cudaGetSymbolAddress((void**)&pstate,   g_state);
    cudaGetSymbolAddress((void**)&pxg,      g_xg);
    cudaGetSymbolAddress((void**)&phg,      g_hg);
    cudaGetSymbolAddress((void**)&ph2,      g_h2);
    cudaGetSymbolAddress((void**)&pstate16, g_state16);
    cudaGetSymbolAddress((void**)&pans16,   g_ans16);
    cudaGetSymbolAddress((void**)&pin16,    g_in16);
    cudaGetSymbolAddress((void**)&ph116,    g_h116);
    cudaGetSymbolAddress((void**)&pwih,     g_wih16);
    cudaGetSymbolAddress((void**)&pwhh,     g_whh16);
    cudaGetSymbolAddress((void**)&paw1,     g_aw116);
    cudaGetSymbolAddress((void**)&paw2,     g_aw216);
    cudaGetSymbolAddress((void**)&phw1,     g_hw116);

    cudaMemsetAsync(pstate,   0, sizeof(float)  * BATCH * LDIM);
    cudaMemsetAsync(pstate16, 0, sizeof(__half) * BATCH * LDIM);
    cudaMemsetAsync(pans16,   0, sizeof(__half) * BATCH * ODIM);

    // One-time fp16 conversions (all element counts are multiples of 256)
    cvt16<<<(BATCH * IDIM) / 256, 256>>>(inputs, pin16);
    cvt16<<<(3 * LDIM * (IDIM + ODIM)) / 256, 256>>>(W_ih, pwih);
    cvt16<<<(3 * LDIM * LDIM) / 256, 256>>>(W_hh, pwhh);
    cvt16<<<(HDIM * (LDIM + ODIM)) / 256, 256>>>(aw1, paw1);
    cvt16<<<(ODIM * HDIM) / 256, 256>>>(aw2, paw2);
    cvt16<<<(HALTH * (LDIM + ODIM)) / 256, 256>>>(hw1, phw1);

    const int MR = BATCH / 128;  // 32

    for (int s = 0; s < OUTER; s++) {
        // x_gates = concat(inputs, ans) @ W_ih^T + b_ih   [B, 3L] fp32
        hgemm<1, 0, 0><<<dim3((3 * LDIM) / 128, MR), 256>>>(
            pin16, IDIM, IDIM, pans16, ODIM, pwih, b_ih,
            pxg, nullptr, 3 * LDIM, IDIM + ODIM);

        for (int i = 0; i < INNER; i++) {
            // h_gates = state @ W_hh^T + b_hh             [B, 3L] fp32
            hgemm<1, 0, 0><<<dim3((3 * LDIM) / 128, MR), 256>>>(
                pstate16, LDIM, LDIM, pstate16, LDIM, pwhh, b_hh,
                phg, nullptr, 3 * LDIM, LDIM);
            gru_kernel<<<(BATCH * LDIM) / 256, 256>>>();
        }

        // h1 = relu(concat(state, ans) @ aw1^T + ab1)     [B, H] fp16 only
        hgemm<0, 1, 1><<<dim3(HDIM / 128, MR), 256>>>(
            pstate16, LDIM, LDIM, pans16, ODIM, paw1, ab1,
            nullptr, ph116, HDIM, LDIM + ODIM);

        // h2 = relu(concat(state, ans) @ hw1^T + hb1)     [B, HALT_H] fp32
        hgemm<1, 0, 1><<<dim3(HALTH / 128, MR), 256>>>(
            pstate16, LDIM, LDIM, pans16, ODIM, phw1, hb1,
            ph2, nullptr, HALTH, LDIM + ODIM);

        // halt = h2 @ hw2^T + hb2                          [B, 2]
        halt_kernel<<<BATCH / 8, 256>>>(hw2, hb2, halt_out + (size_t)s * BATCH * 2);

        // logits -> out (fp32); ans16 = half(tanh(logits))  (LAST: overwrites ans)
        hgemm<1, 1, 2><<<dim3(ODIM / 128, MR), 256>>>(
            ph116, HDIM, HDIM, ph116, HDIM, paw2, ab2,
            ans_out + (size_t)s * BATCH * ODIM, pans16, ODIM, HDIM);
    }
}

// round 5
// speedup vs baseline: 2.6210x; 1.0334x over previous
#include <cuda_runtime.h>
#include <cuda_fp16.h>
#include <cstdint>
#include <math.h>

#define BATCH   4096
#define IDIM    1024
#define LDIM    1024
#define HDIM    2048
#define ODIM    512
#define HALTH   1024
#define OUTER   8
#define INNER   4

// ---------------------------------------------------------------------------
// Device-global scratch (no allocation allowed)
// ---------------------------------------------------------------------------
__device__ float  g_state[BATCH * LDIM];

__device__ __half g_xg16[BATCH * 3 * LDIM];
__device__ __half g_hg16[BATCH * 3 * LDIM];
__device__ __half g_h216[BATCH * HALTH];

__device__ __half g_state16[BATCH * LDIM];
__device__ __half g_ans16[BATCH * ODIM];
__device__ __half g_in16[BATCH * IDIM];
__device__ __half g_h116[BATCH * HDIM];

__device__ __half g_wih16[3 * LDIM * (IDIM + ODIM)];
__device__ __half g_whh16[3 * LDIM * LDIM];
__device__ __half g_aw116[HDIM * (LDIM + ODIM)];
__device__ __half g_aw216[ODIM * HDIM];
__device__ __half g_hw116[HALTH * (LDIM + ODIM)];

__device__ __forceinline__ uint32_t smem_u32(const void* p) {
    uint32_t a;
    asm("{ .reg .u64 t; cvta.to.shared.u64 t, %1; cvt.u32.u64 %0, t; }" : "=r"(a) : "l"(p));
    return a;
}

// Swizzled smem layout: rows of 32 halves (64B) packed into 128B lines.
// 16B-unit offset for (row r, 16B-chunk c in 0..3). Conflict-free for both
// cp.async fill and ldmatrix reads (validated round 4).
__device__ __forceinline__ uint32_t soff(int r, int c) {
    return (uint32_t)((((r >> 1) * 8) + ((((r & 1) << 2) | c) ^ ((r >> 1) & 7))) << 4);
}

// ---------------------------------------------------------------------------
// fp16 tensor-core GEMM:  C = act( concat(A1,A2) @ W^T + bias )
//   BM=128, BN in {128,256}; 256 threads = 8 warps; warp tile (16*NW) x 64
//   where NW = BN/64 (warps across N). 3-stage cp.async, ldmatrix.x4,
//   mma.m16n8k16. W32 -> C fp32, W16 -> C2 fp16. ACT: 0 none, 1 relu,
//   2 logits (C raw fp32, C2 = half(tanh)).
// ---------------------------------------------------------------------------
template <int BN, int W32, int W16, int ACT>
__global__ void __launch_bounds__(256)
hgemm(const __half* __restrict__ A1, int lda1, int K1,
      const __half* __restrict__ A2, int lda2,
      const __half* __restrict__ W,
      const float* __restrict__ bias,
      float* __restrict__ C,
      __half* __restrict__ C2,
      int N, int K)
{
    constexpr int NW    = BN / 64;          // warps across N (2 or 4)
    constexpr int MI    = NW;               // m16 fragments per warp (2 or 4)
    constexpr int STAGE = 8192 + BN * 64;   // bytes per stage (A + B)

    extern __shared__ __align__(128) char smem[];
    const uint32_t sb = smem_u32(smem);

    const int tid  = threadIdx.x;
    const int lane = tid & 31;
    const int warp = tid >> 5;
    const int wm   = warp / NW;
    const int wn   = warp % NW;
    const int row0 = blockIdx.y * 128;
    const int col0 = blockIdx.x * BN;

    float c[MI][8][4];
#pragma unroll
    for (int i = 0; i < MI; i++)
#pragma unroll
        for (int j = 0; j < 8; j++)
#pragma unroll
            for (int k = 0; k < 4; k++) c[i][j][k] = 0.0f;

    const int nc = K >> 5;

    auto load_chunk = [&](int t) {
        const int st = t % 3;
        const int k0 = t << 5;
        const __half* Ab;
        int lda;
        if (k0 < K1) { Ab = A1 + k0;        lda = lda1; }
        else         { Ab = A2 + (k0 - K1); lda = lda2; }
        const uint32_t aB = sb + st * STAGE;
        const uint32_t bB = aB + 8192;
#pragma unroll
        for (int j = 0; j < 2; j++) {                  // A: 128 rows x 4 chunks
            const int idx = j * 256 + tid;
            const int r = idx >> 2, cc = idx & 3;
            const uint32_t da = aB + soff(r, cc);
            const __half* ga = Ab + (size_t)(row0 + r) * lda + cc * 8;
            asm volatile("cp.async.cg.shared.global [%0], [%1], 16;" :: "r"(da), "l"(ga));
        }
#pragma unroll
        for (int j = 0; j < NW; j++) {                 // B: BN rows x 4 chunks
            const int idx = j * 256 + tid;
            const int r = idx >> 2, cc = idx & 3;
            const uint32_t db = bB + soff(r, cc);
            const __half* gb = W + (size_t)(col0 + r) * K + k0 + cc * 8;
            asm volatile("cp.async.cg.shared.global [%0], [%1], 16;" :: "r"(db), "l"(gb));
        }
        asm volatile("cp.async.commit_group;");
    };

    load_chunk(0);
    load_chunk(1);

    for (int t = 0; t < nc; t++) {
        if (t + 2 <= nc) asm volatile("cp.async.wait_group 1;");
        else             asm volatile("cp.async.wait_group 0;");
        __syncthreads();
        if (t + 2 < nc) load_chunk(t + 2);

        const uint32_t aB = sb + (t % 3) * STAGE;
        const uint32_t bB = aB + 8192;

#pragma unroll
        for (int kh = 0; kh < 2; kh++) {
            uint32_t a[MI][4];
#pragma unroll
            for (int mi = 0; mi < MI; mi++) {
                const int row = wm * (16 * MI) + mi * 16 + (lane & 15);
                const int cc  = kh * 2 + (lane >> 4);
                const uint32_t ad = aB + soff(row, cc);
                asm volatile("ldmatrix.sync.aligned.m8n8.x4.shared.b16 {%0,%1,%2,%3}, [%4];"
                             : "=r"(a[mi][0]), "=r"(a[mi][1]), "=r"(a[mi][2]), "=r"(a[mi][3])
                             : "r"(ad));
            }
            uint32_t b[4][4];
#pragma unroll
            for (int ng = 0; ng < 4; ng++) {
                const int row = wn * 64 + ng * 16 + (lane & 7) + ((lane >> 4) << 3);
                const int cc  = kh * 2 + ((lane >> 3) & 1);
                const uint32_t bd = bB + soff(row, cc);
                asm volatile("ldmatrix.sync.aligned.m8n8.x4.shared.b16 {%0,%1,%2,%3}, [%4];"
                             : "=r"(b[ng][0]), "=r"(b[ng][1]), "=r"(b[ng][2]), "=r"(b[ng][3])
                             : "r"(bd));
            }
#pragma unroll
            for (int mi = 0; mi < MI; mi++)
#pragma unroll
                for (int ng = 0; ng < 4; ng++) {
                    asm volatile(
                        "mma.sync.aligned.m16n8k16.row.col.f32.f16.f16.f32 "
                        "{%0,%1,%2,%3},{%4,%5,%6,%7},{%8,%9},{%0,%1,%2,%3};"
                        : "+f"(c[mi][2 * ng][0]), "+f"(c[mi][2 * ng][1]),
                          "+f"(c[mi][2 * ng][2]), "+f"(c[mi][2 * ng][3])
                        : "r"(a[mi][0]), "r"(a[mi][1]), "r"(a[mi][2]), "r"(a[mi][3]),
                          "r"(b[ng][0]), "r"(b[ng][1]));
                    asm volatile(
                        "mma.sync.aligned.m16n8k16.row.col.f32.f16.f16.f32 "
                        "{%0,%1,%2,%3},{%4,%5,%6,%7},{%8,%9},{%0,%1,%2,%3};"
                        : "+f"(c[mi][2 * ng + 1][0]), "+f"(c[mi][2 * ng + 1][1]),
                          "+f"(c[mi][2 * ng + 1][2]), "+f"(c[mi][2 * ng + 1][3])
                        : "r"(a[mi][0]), "r"(a[mi][1]), "r"(a[mi][2]), "r"(a[mi][3]),
                          "r"(b[ng][2]), "r"(b[ng][3]));
                }
        }
    }

    // Epilogue (direct stores)
#pragma unroll
    for (int mi = 0; mi < MI; mi++) {
        const int r0 = row0 + wm * (16 * MI) + mi * 16 + (lane >> 2);
#pragma unroll
        for (int ni = 0; ni < 8; ni++) {
            const int col = col0 + wn * 64 + ni * 8 + (lane & 3) * 2;
            const float b0 = __ldg(&bias[col]);
            const float b1 = __ldg(&bias[col + 1]);
            float v00 = c[mi][ni][0] + b0;
            float v01 = c[mi][ni][1] + b1;
            float v10 = c[mi][ni][2] + b0;
            float v11 = c[mi][ni][3] + b1;
            if (ACT == 1) {
                v00 = fmaxf(v00, 0.0f); v01 = fmaxf(v01, 0.0f);
                v10 = fmaxf(v10, 0.0f); v11 = fmaxf(v11, 0.0f);
            }
            const size_t i0 = (size_t)r0 * N + col;
            const size_t i1 = (size_t)(r0 + 8) * N + col;
            if (W32) {
                C[i0] = v00; C[i0 + 1] = v01;
                C[i1] = v10; C[i1 + 1] = v11;
            }
            if (W16) {
                float w00 = v00, w01 = v01, w10 = v10, w11 = v11;
                if (ACT == 2) {
                    w00 = tanhf(v00); w01 = tanhf(v01);
                    w10 = tanhf(v10); w11 = tanhf(v11);
                }
                *(__half2*)&C2[i0] = __floats2half2_rn(w00, w01);
                *(__half2*)&C2[i1] = __floats2half2_rn(w10, w11);
            }
        }
    }
}

// ---------------------------------------------------------------------------
// Elementwise / small kernels
// ---------------------------------------------------------------------------
__global__ void cvt16(const float* __restrict__ src, __half* __restrict__ dst) {
    const int i = blockIdx.x * blockDim.x + threadIdx.x;
    dst[i] = __float2half_rn(src[i]);
}

// GRU update, 2 elements/thread, fp16 gates, fp32 state math.
__global__ void gru_kernel() {
    const int idx = blockIdx.x * blockDim.x + threadIdx.x;   // BATCH*LDIM/2
    const int row = idx >> 9;            // LDIM/2 = 512 half2 per row
    const int p   = idx & 511;
    const __half2* xg = (const __half2*)g_xg16 + (size_t)row * 1536;
    const __half2* hg = (const __half2*)g_hg16 + (size_t)row * 1536;
    const float2 xr = __half22float2(xg[p]);
    const float2 xz = __half22float2(xg[512 + p]);
    const float2 xn = __half22float2(xg[1024 + p]);
    const float2 hr = __half22float2(hg[p]);
    const float2 hz = __half22float2(hg[512 + p]);
    const float2 hn = __half22float2(hg[1024 + p]);
    const float2 s  = ((const float2*)g_state)[idx];

    const float r0 = 1.0f / (1.0f + expf(-(xr.x + hr.x)));
    const float z0 = 1.0f / (1.0f + expf(-(xz.x + hz.x)));
    const float n0 = tanhf(xn.x + r0 * hn.x);
    const float r1 = 1.0f / (1.0f + expf(-(xr.y + hr.y)));
    const float z1 = 1.0f / (1.0f + expf(-(xz.y + hz.y)));
    const float n1 = tanhf(xn.y + r1 * hn.y);

    float2 ns;
    ns.x = (1.0f - z0) * n0 + z0 * s.x;
    ns.y = (1.0f - z1) * n1 + z1 * s.y;
    ((float2*)g_state)[idx] = ns;
    ((__half2*)g_state16)[idx] = __floats2half2_rn(ns.x, ns.y);
}

__global__ void halt_kernel(const float* __restrict__ hw2,
                            const float* __restrict__ hb2,
                            float* __restrict__ out) {
    const int row  = blockIdx.x * (blockDim.x >> 5) + (threadIdx.x >> 5);
    const int lane = threadIdx.x & 31;
    const __half2* h = (const __half2*)(g_h216 + (size_t)row * HALTH);
    const float2* w0 = (const float2*)hw2;          // row 0
    const float2* w1 = (const float2*)(hw2 + HALTH); // row 1
    float s0 = 0.0f, s1 = 0.0f;
    for (int k = lane; k < HALTH / 2; k += 32) {
        const float2 v  = __half22float2(h[k]);
        const float2 a0 = w0[k];
        const float2 a1 = w1[k];
        s0 += v.x * a0.x + v.y * a0.y;
        s1 += v.x * a1.x + v.y * a1.y;
    }
#pragma unroll
    for (int o = 16; o > 0; o >>= 1) {
        s0 += __shfl_down_sync(0xFFFFFFFFu, s0, o);
        s1 += __shfl_down_sync(0xFFFFFFFFu, s1, o);
    }
    if (lane == 0) {
        out[(size_t)row * 2]     = s0 + hb2[0];
        out[(size_t)row * 2 + 1] = s1 + hb2[1];
    }
}

// ---------------------------------------------------------------------------
// Host orchestration
// ---------------------------------------------------------------------------
extern "C" void kernel_launch(void* const* d_in, const int* in_sizes, int n_in,
                              void* d_out, int out_size)
{
    const float* inputs = (const float*)d_in[0];
    const float* W_ih   = (const float*)d_in[1];
    const float* W_hh   = (const float*)d_in[2];
    const float* b_ih   = (const float*)d_in[3];
    const float* b_hh   = (const float*)d_in[4];
    const float* aw1    = (const float*)d_in[5];
    const float* ab1    = (const float*)d_in[6];
    const float* aw2    = (const float*)d_in[7];
    const float* ab2    = (const float*)d_in[8];
    const float* hw1    = (const float*)d_in[9];
    const float* hb1    = (const float*)d_in[10];
    const float* hw2    = (const float*)d_in[11];
    const float* hb2    = (const float*)d_in[12];

    float* out = (float*)d_out;
    float* ans_out  = out;                                  // [8, 4096, 512]
    float* halt_out = out + (size_t)OUTER * BATCH * ODIM;   // [8, 4096, 2]

    float *pstate;
    __half *pxg, *phg, *ph216;
    __half *pstate16, *pans16, *pin16, *ph116;
    __half *pwih, *pwhh, *paw1, *paw2, *phw1;
    cudaGetSymbolAddress((void**)&pstate,   g_state);
    cudaGetSymbolAddress((void**)&pxg,      g_xg16);
    cudaGetSymbolAddress((void**)&phg,      g_hg16);
    cudaGetSymbolAddress((void**)&ph216,    g_h216);
    cudaGetSymbolAddress((void**)&pstate16, g_state16);
    cudaGetSymbolAddress((void**)&pans16,   g_ans16);
    cudaGetSymbolAddress((void**)&pin16,    g_in16);
    cudaGetSymbolAddress((void**)&ph116,    g_h116);
    cudaGetSymbolAddress((void**)&pwih,     g_wih16);
    cudaGetSymbolAddress((void**)&pwhh,     g_whh16);
    cudaGetSymbolAddress((void**)&paw1,     g_aw116);
    cudaGetSymbolAddress((void**)&paw2,     g_aw216);
    cudaGetSymbolAddress((void**)&phw1,     g_hw116);

    // Dynamic smem opt-in (3 stages)
    const int SM256 = 3 * (8192 + 256 * 64);  // 73728
    const int SM128 = 3 * (8192 + 128 * 64);  // 49152
    cudaFuncSetAttribute(hgemm<256, 0, 1, 0>, cudaFuncAttributeMaxDynamicSharedMemorySize, SM256);
    cudaFuncSetAttribute(hgemm<256, 0, 1, 1>, cudaFuncAttributeMaxDynamicSharedMemorySize, SM256);
    cudaFuncSetAttribute(hgemm<128, 1, 1, 2>, cudaFuncAttributeMaxDynamicSharedMemorySize, SM128);

    cudaMemsetAsync(pstate,   0, sizeof(float)  * BATCH * LDIM);
    cudaMemsetAsync(pstate16, 0, sizeof(__half) * BATCH * LDIM);
    cudaMemsetAsync(pans16,   0, sizeof(__half) * BATCH * ODIM);

    // One-time fp16 conversions
    cvt16<<<(BATCH * IDIM) / 256, 256>>>(inputs, pin16);
    cvt16<<<(3 * LDIM * (IDIM + ODIM)) / 256, 256>>>(W_ih, pwih);
    cvt16<<<(3 * LDIM * LDIM) / 256, 256>>>(W_hh, pwhh);
    cvt16<<<(HDIM * (LDIM + ODIM)) / 256, 256>>>(aw1, paw1);
    cvt16<<<(ODIM * HDIM) / 256, 256>>>(aw2, paw2);
    cvt16<<<(HALTH * (LDIM + ODIM)) / 256, 256>>>(hw1, phw1);

    const int MR = BATCH / 128;  // 32

    for (int s = 0; s < OUTER; s++) {
        // x_gates = concat(inputs, ans) @ W_ih^T + b_ih   [B, 3L] fp16
        hgemm<256, 0, 1, 0><<<dim3((3 * LDIM) / 256, MR), 256, SM256>>>(
            pin16, IDIM, IDIM, pans16, ODIM, pwih, b_ih,
            nullptr, pxg, 3 * LDIM, IDIM + ODIM);

        for (int i = 0; i < INNER; i++) {
            // h_gates = state @ W_hh^T + b_hh             [B, 3L] fp16
            hgemm<256, 0, 1, 0><<<dim3((3 * LDIM) / 256, MR), 256, SM256>>>(
                pstate16, LDIM, LDIM, pstate16, LDIM, pwhh, b_hh,
                nullptr, phg, 3 * LDIM, LDIM);
            gru_kernel<<<(BATCH * LDIM / 2) / 256, 256>>>();
        }

        // h1 = relu(concat(state, ans) @ aw1^T + ab1)     [B, H] fp16
        hgemm<256, 0, 1, 1><<<dim3(HDIM / 256, MR), 256, SM256>>>(
            pstate16, LDIM, LDIM, pans16, ODIM, paw1, ab1,
            nullptr, ph116, HDIM, LDIM + ODIM);

        // h2 = relu(concat(state, ans) @ hw1^T + hb1)     [B, HALT_H] fp16
        hgemm<256, 0, 1, 1><<<dim3(HALTH / 256, MR), 256, SM256>>>(
            pstate16, LDIM, LDIM, pans16, ODIM, phw1, hb1,
            nullptr, ph216, HALTH, LDIM + ODIM);

        // halt = h2 @ hw2^T + hb2                          [B, 2]
        halt_kernel<<<BATCH / 8, 256>>>(hw2, hb2, halt_out + (size_t)s * BATCH * 2);

        // logits -> out (fp32); ans16 = half(tanh(logits))  (LAST: overwrites ans)
        hgemm<128, 1, 1, 2><<<dim3(ODIM / 128, MR), 256, SM128>>>(
            ph116, HDIM, HDIM, ph116, HDIM, paw2, ab2,
            ans_out + (size_t)s * BATCH * ODIM, pans16, ODIM, HDIM);
    }
}

// round 6
// speedup vs baseline: 2.7399x; 1.0454x over previous
#include <cuda_runtime.h>
#include <cuda_fp16.h>
#include <cstdint>
#include <math.h>

#define BATCH   4096
#define IDIM    1024
#define LDIM    1024
#define HDIM    2048
#define ODIM    512
#define HALTH   1024
#define OUTER   8
#define INNER   4

// ---------------------------------------------------------------------------
// Device-global scratch (no allocation allowed)
// ---------------------------------------------------------------------------
__device__ float  g_state[BATCH * LDIM];

__device__ __half g_xg16[BATCH * 3 * LDIM];
__device__ __half g_hg16[BATCH * 3 * LDIM];
__device__ __half g_h216[BATCH * HALTH];

__device__ __half g_state16[BATCH * LDIM];
__device__ __half g_ans16[BATCH * ODIM];
__device__ __half g_in16[BATCH * IDIM];
__device__ __half g_h116[BATCH * HDIM];

__device__ __half g_wih16[3 * LDIM * (IDIM + ODIM)];
__device__ __half g_whh16[3 * LDIM * LDIM];
__device__ __half g_aw116[HDIM * (LDIM + ODIM)];
__device__ __half g_aw216[ODIM * HDIM];
__device__ __half g_hw116[HALTH * (LDIM + ODIM)];

__device__ __forceinline__ uint32_t smem_u32(const void* p) {
    uint32_t a;
    asm("{ .reg .u64 t; cvta.to.shared.u64 t, %1; cvt.u32.u64 %0, t; }" : "=r"(a) : "l"(p));
    return a;
}

// Swizzled smem layout: rows of 32 halves (64B) packed into 128B lines.
// 16B-unit offset for (row r, 16B-chunk c in 0..3). Conflict-free for both
// cp.async fill and ldmatrix reads (validated rounds 4-5).
__device__ __forceinline__ uint32_t soff(int r, int c) {
    return (uint32_t)((((r >> 1) * 8) + ((((r & 1) << 2) | c) ^ ((r >> 1) & 7))) << 4);
}

// ---------------------------------------------------------------------------
// fp16 tensor-core GEMM:  C = act( concat(A1,A2) @ W^T + bias )
//   Warp grid WM x WN; warp tile (16*MI) x (16*NG); BM = WM*MI*16, BN = WN*NG*16.
//   3-stage cp.async pipeline, ldmatrix.x4, mma.m16n8k16, fp32 accum.
//   W32 -> C fp32, W16 -> C2 fp16. ACT: 0 none, 1 relu, 2 logits(C raw, C2 tanh16)
// ---------------------------------------------------------------------------
template <int WM, int WN, int MI, int NG, int W32, int W16, int ACT>
__global__ void __launch_bounds__(WM * WN * 32)
hgemm(const __half* __restrict__ A1, int lda1, int K1,
      const __half* __restrict__ A2, int lda2,
      const __half* __restrict__ W,
      const float* __restrict__ bias,
      float* __restrict__ C,
      __half* __restrict__ C2,
      int N, int K)
{
    constexpr int THREADS = WM * WN * 32;
    constexpr int BM      = WM * MI * 16;
    constexpr int BN      = WN * NG * 16;
    constexpr int NI      = 2 * NG;
    constexpr int STAGE   = (BM + BN) * 64;     // bytes per pipeline stage
    constexpr int NLOAD   = (BM + BN) * 4 / THREADS;  // 16B chunks per thread

    extern __shared__ __align__(128) char smem[];
    const uint32_t sb = smem_u32(smem);

    const int tid  = threadIdx.x;
    const int lane = tid & 31;
    const int warp = tid >> 5;
    const int wm   = warp / WN;
    const int wn   = warp % WN;
    const int row0 = blockIdx.y * BM;
    const int col0 = blockIdx.x * BN;

    float c[MI][NI][4];
#pragma unroll
    for (int i = 0; i < MI; i++)
#pragma unroll
        for (int j = 0; j < NI; j++)
#pragma unroll
            for (int k = 0; k < 4; k++) c[i][j][k] = 0.0f;

    const int nc = K >> 5;

    auto load_chunk = [&](int t) {
        const int st = t % 3;
        const int k0 = t << 5;
        const __half* Ab;
        int lda;
        if (k0 < K1) { Ab = A1 + k0;        lda = lda1; }
        else         { Ab = A2 + (k0 - K1); lda = lda2; }
        const uint32_t aB = sb + st * STAGE;
        const uint32_t bB = aB + BM * 64;
#pragma unroll
        for (int j = 0; j < NLOAD; j++) {
            const int idx = j * THREADS + tid;
            if (idx < BM * 4) {
                const int r = idx >> 2, cc = idx & 3;
                const uint32_t d = aB + soff(r, cc);
                const __half* g = Ab + (size_t)(row0 + r) * lda + cc * 8;
                asm volatile("cp.async.cg.shared.global [%0], [%1], 16;" :: "r"(d), "l"(g));
            } else {
                const int li = idx - BM * 4;
                const int r = li >> 2, cc = li & 3;
                const uint32_t d = bB + soff(r, cc);
                const __half* g = W + (size_t)(col0 + r) * K + k0 + cc * 8;
                asm volatile("cp.async.cg.shared.global [%0], [%1], 16;" :: "r"(d), "l"(g));
            }
        }
        asm volatile("cp.async.commit_group;");
    };

    load_chunk(0);
    load_chunk(1);

    for (int t = 0; t < nc; t++) {
        if (t + 2 <= nc) asm volatile("cp.async.wait_group 1;");
        else             asm volatile("cp.async.wait_group 0;");
        __syncthreads();
        if (t + 2 < nc) load_chunk(t + 2);

        const uint32_t aB = sb + (t % 3) * STAGE;
        const uint32_t bB = aB + BM * 64;

#pragma unroll
        for (int kh = 0; kh < 2; kh++) {
            uint32_t a[MI][4];
#pragma unroll
            for (int mi = 0; mi < MI; mi++) {
                const int row = wm * (16 * MI) + mi * 16 + (lane & 15);
                const int cc  = kh * 2 + (lane >> 4);
                const uint32_t ad = aB + soff(row, cc);
                asm volatile("ldmatrix.sync.aligned.m8n8.x4.shared.b16 {%0,%1,%2,%3}, [%4];"
                             : "=r"(a[mi][0]), "=r"(a[mi][1]), "=r"(a[mi][2]), "=r"(a[mi][3])
                             : "r"(ad));
            }
            uint32_t b[NG][4];
#pragma unroll
            for (int ng = 0; ng < NG; ng++) {
                const int row = wn * (16 * NG) + ng * 16 + (lane & 7) + ((lane >> 4) << 3);
                const int cc  = kh * 2 + ((lane >> 3) & 1);
                const uint32_t bd = bB + soff(row, cc);
                asm volatile("ldmatrix.sync.aligned.m8n8.x4.shared.b16 {%0,%1,%2,%3}, [%4];"
                             : "=r"(b[ng][0]), "=r"(b[ng][1]), "=r"(b[ng][2]), "=r"(b[ng][3])
                             : "r"(bd));
            }
#pragma unroll
            for (int mi = 0; mi < MI; mi++)
#pragma unroll
                for (int ng = 0; ng < NG; ng++) {
                    asm volatile(
                        "mma.sync.aligned.m16n8k16.row.col.f32.f16.f16.f32 "
                        "{%0,%1,%2,%3},{%4,%5,%6,%7},{%8,%9},{%0,%1,%2,%3};"
                        : "+f"(c[mi][2 * ng][0]), "+f"(c[mi][2 * ng][1]),
                          "+f"(c[mi][2 * ng][2]), "+f"(c[mi][2 * ng][3])
                        : "r"(a[mi][0]), "r"(a[mi][1]), "r"(a[mi][2]), "r"(a[mi][3]),
                          "r"(b[ng][0]), "r"(b[ng][1]));
                    asm volatile(
                        "mma.sync.aligned.m16n8k16.row.col.f32.f16.f16.f32 "
                        "{%0,%1,%2,%3},{%4,%5,%6,%7},{%8,%9},{%0,%1,%2,%3};"
                        : "+f"(c[mi][2 * ng + 1][0]), "+f"(c[mi][2 * ng + 1][1]),
                          "+f"(c[mi][2 * ng + 1][2]), "+f"(c[mi][2 * ng + 1][3])
                        : "r"(a[mi][0]), "r"(a[mi][1]), "r"(a[mi][2]), "r"(a[mi][3]),
                          "r"(b[ng][2]), "r"(b[ng][3]));
                }
        }
    }

    // Epilogue (direct stores)
#pragma unroll
    for (int mi = 0; mi < MI; mi++) {
        const int r0 = row0 + wm * (16 * MI) + mi * 16 + (lane >> 2);
#pragma unroll
        for (int ni = 0; ni < NI; ni++) {
            const int col = col0 + wn * (16 * NG) + ni * 8 + (lane & 3) * 2;
            const float b0 = __ldg(&bias[col]);
            const float b1 = __ldg(&bias[col + 1]);
            float v00 = c[mi][ni][0] + b0;
            float v01 = c[mi][ni][1] + b1;
            float v10 = c[mi][ni][2] + b0;
            float v11 = c[mi][ni][3] + b1;
            if (ACT == 1) {
                v00 = fmaxf(v00, 0.0f); v01 = fmaxf(v01, 0.0f);
                v10 = fmaxf(v10, 0.0f); v11 = fmaxf(v11, 0.0f);
            }
            const size_t i0 = (size_t)r0 * N + col;
            const size_t i1 = (size_t)(r0 + 8) * N + col;
            if (W32) {
                C[i0] = v00; C[i0 + 1] = v01;
                C[i1] = v10; C[i1 + 1] = v11;
            }
            if (W16) {
                float w00 = v00, w01 = v01, w10 = v10, w11 = v11;
                if (ACT == 2) {
                    w00 = tanhf(v00); w01 = tanhf(v01);
                    w10 = tanhf(v10); w11 = tanhf(v11);
                }
                *(__half2*)&C2[i0] = __floats2half2_rn(w00, w01);
                *(__half2*)&C2[i1] = __floats2half2_rn(w10, w11);
            }
        }
    }
}

// ---------------------------------------------------------------------------
// Elementwise / small kernels
// ---------------------------------------------------------------------------
__global__ void cvt16(const float* __restrict__ src, __half* __restrict__ dst) {
    const int i = blockIdx.x * blockDim.x + threadIdx.x;
    dst[i] = __float2half_rn(src[i]);
}

// GRU update, 2 elements/thread, fp16 gates, fp32 state math.
__global__ void gru_kernel() {
    const int idx = blockIdx.x * blockDim.x + threadIdx.x;   // BATCH*LDIM/2
    const int row = idx >> 9;            // LDIM/2 = 512 half2 per row
    const int p   = idx & 511;
    const __half2* xg = (const __half2*)g_xg16 + (size_t)row * 1536;
    const __half2* hg = (const __half2*)g_hg16 + (size_t)row * 1536;
    const float2 xr = __half22float2(xg[p]);
    const float2 xz = __half22float2(xg[512 + p]);
    const float2 xn = __half22float2(xg[1024 + p]);
    const float2 hr = __half22float2(hg[p]);
    const float2 hz = __half22float2(hg[512 + p]);
    const float2 hn = __half22float2(hg[1024 + p]);
    const float2 s  = ((const float2*)g_state)[idx];

    const float r0 = 1.0f / (1.0f + expf(-(xr.x + hr.x)));
    const float z0 = 1.0f / (1.0f + expf(-(xz.x + hz.x)));
    const float n0 = tanhf(xn.x + r0 * hn.x);
    const float r1 = 1.0f / (1.0f + expf(-(xr.y + hr.y)));
    const float z1 = 1.0f / (1.0f + expf(-(xz.y + hz.y)));
    const float n1 = tanhf(xn.y + r1 * hn.y);

    float2 ns;
    ns.x = (1.0f - z0) * n0 + z0 * s.x;
    ns.y = (1.0f - z1) * n1 + z1 * s.y;
    ((float2*)g_state)[idx] = ns;
    ((__half2*)g_state16)[idx] = __floats2half2_rn(ns.x, ns.y);
}

__global__ void halt_kernel(const float* __restrict__ hw2,
                            const float* __restrict__ hb2,
                            float* __restrict__ out) {
    const int row  = blockIdx.x * (blockDim.x >> 5) + (threadIdx.x >> 5);
    const int lane = threadIdx.x & 31;
    const __half2* h = (const __half2*)(g_h216 + (size_t)row * HALTH);
    const float2* w0 = (const float2*)hw2;           // row 0
    const float2* w1 = (const float2*)(hw2 + HALTH); // row 1
    float s0 = 0.0f, s1 = 0.0f;
    for (int k = lane; k < HALTH / 2; k += 32) {
        const float2 v  = __half22float2(h[k]);
        const float2 a0 = w0[k];
        const float2 a1 = w1[k];
        s0 += v.x * a0.x + v.y * a0.y;
        s1 += v.x * a1.x + v.y * a1.y;
    }
#pragma unroll
    for (int o = 16; o > 0; o >>= 1) {
        s0 += __shfl_down_sync(0xFFFFFFFFu, s0, o);
        s1 += __shfl_down_sync(0xFFFFFFFFu, s1, o);
    }
    if (lane == 0) {
        out[(size_t)row * 2]     = s0 + hb2[0];
        out[(size_t)row * 2 + 1] = s1 + hb2[1];
    }
}

// ---------------------------------------------------------------------------
// Host orchestration
// ---------------------------------------------------------------------------
extern "C" void kernel_launch(void* const* d_in, const int* in_sizes, int n_in,
                              void* d_out, int out_size)
{
    const float* inputs = (const float*)d_in[0];
    const float* W_ih   = (const float*)d_in[1];
    const float* W_hh   = (const float*)d_in[2];
    const float* b_ih   = (const float*)d_in[3];
    const float* b_hh   = (const float*)d_in[4];
    const float* aw1    = (const float*)d_in[5];
    const float* ab1    = (const float*)d_in[6];
    const float* aw2    = (const float*)d_in[7];
    const float* ab2    = (const float*)d_in[8];
    const float* hw1    = (const float*)d_in[9];
    const float* hb1    = (const float*)d_in[10];
    const float* hw2    = (const float*)d_in[11];
    const float* hb2    = (const float*)d_in[12];

    float* out = (float*)d_out;
    float* ans_out  = out;                                  // [8, 4096, 512]
    float* halt_out = out + (size_t)OUTER * BATCH * ODIM;   // [8, 4096, 2]

    float *pstate;
    __half *pxg, *phg, *ph216;
    __half *pstate16, *pans16, *pin16, *ph116;
    __half *pwih, *pwhh, *paw1, *paw2, *phw1;
    cudaGetSymbolAddress((void**)&pstate,   g_state);
    cudaGetSymbolAddress((void**)&pxg,      g_xg16);
    cudaGetSymbolAddress((void**)&phg,      g_hg16);
    cudaGetSymbolAddress((void**)&ph216,    g_h216);
    cudaGetSymbolAddress((void**)&pstate16, g_state16);
    cudaGetSymbolAddress((void**)&pans16,   g_ans16);
    cudaGetSymbolAddress((void**)&pin16,    g_in16);
    cudaGetSymbolAddress((void**)&ph116,    g_h116);
    cudaGetSymbolAddress((void**)&pwih,     g_wih16);
    cudaGetSymbolAddress((void**)&pwhh,     g_whh16);
    cudaGetSymbolAddress((void**)&paw1,     g_aw116);
    cudaGetSymbolAddress((void**)&paw2,     g_aw216);
    cudaGetSymbolAddress((void**)&phw1,     g_hw116);

    // Big config: 512 thr, BM=256, BN=128 (WM=4,WN=4,MI=4,NG=2)
    // Small (logits): 256 thr, BM=128, BN=128 (WM=4,WN=2,MI=2,NG=4)
    const int SMB = 3 * (256 + 128) * 64;  // 73728
    const int SMS = 3 * (128 + 128) * 64;  // 49152
    cudaFuncSetAttribute(hgemm<4, 4, 4, 2, 0, 1, 0>, cudaFuncAttributeMaxDynamicSharedMemorySize, SMB);
    cudaFuncSetAttribute(hgemm<4, 4, 4, 2, 0, 1, 1>, cudaFuncAttributeMaxDynamicSharedMemorySize, SMB);
    cudaFuncSetAttribute(hgemm<4, 2, 2, 4, 1, 1, 2>, cudaFuncAttributeMaxDynamicSharedMemorySize, SMS);

    cudaMemsetAsync(pstate,   0, sizeof(float)  * BATCH * LDIM);
    cudaMemsetAsync(pstate16, 0, sizeof(__half) * BATCH * LDIM);
    cudaMemsetAsync(pans16,   0, sizeof(__half) * BATCH * ODIM);

    // One-time fp16 conversions
    cvt16<<<(BATCH * IDIM) / 256, 256>>>(inputs, pin16);
    cvt16<<<(3 * LDIM * (IDIM + ODIM)) / 256, 256>>>(W_ih, pwih);
    cvt16<<<(3 * LDIM * LDIM) / 256, 256>>>(W_hh, pwhh);
    cvt16<<<(HDIM * (LDIM + ODIM)) / 256, 256>>>(aw1, paw1);
    cvt16<<<(ODIM * HDIM) / 256, 256>>>(aw2, paw2);
    cvt16<<<(HALTH * (LDIM + ODIM)) / 256, 256>>>(hw1, phw1);

    const int MRB = BATCH / 256;  // 16

    for (int s = 0; s < OUTER; s++) {
        // x_gates = concat(inputs, ans) @ W_ih^T + b_ih   [B, 3L] fp16
        hgemm<4, 4, 4, 2, 0, 1, 0><<<dim3((3 * LDIM) / 128, MRB), 512, SMB>>>(
            pin16, IDIM, IDIM, pans16, ODIM, pwih, b_ih,
            nullptr, pxg, 3 * LDIM, IDIM + ODIM);

        for (int i = 0; i < INNER; i++) {
            // h_gates = state @ W_hh^T + b_hh             [B, 3L] fp16
            hgemm<4, 4, 4, 2, 0, 1, 0><<<dim3((3 * LDIM) / 128, MRB), 512, SMB>>>(
                pstate16, LDIM, LDIM, pstate16, LDIM, pwhh, b_hh,
                nullptr, phg, 3 * LDIM, LDIM);
            gru_kernel<<<(BATCH * LDIM / 2) / 256, 256>>>();
        }

        // h1 = relu(concat(state, ans) @ aw1^T + ab1)     [B, H] fp16
        hgemm<4, 4, 4, 2, 0, 1, 1><<<dim3(HDIM / 128, MRB), 512, SMB>>>(
            pstate16, LDIM, LDIM, pans16, ODIM, paw1, ab1,
            nullptr, ph116, HDIM, LDIM + ODIM);

        // h2 = relu(concat(state, ans) @ hw1^T + hb1)     [B, HALT_H] fp16
        hgemm<4, 4, 4, 2, 0, 1, 1><<<dim3(HALTH / 128, MRB), 512, SMB>>>(
            pstate16, LDIM, LDIM, pans16, ODIM, phw1, hb1,
            nullptr, ph216, HALTH, LDIM + ODIM);

        // halt = h2 @ hw2^T + hb2                          [B, 2]
        halt_kernel<<<BATCH / 8, 256>>>(hw2, hb2, halt_out + (size_t)s * BATCH * 2);

        // logits -> out (fp32); ans16 = half(tanh(logits))  (LAST: overwrites ans)
        hgemm<4, 2, 2, 4, 1, 1, 2><<<dim3(ODIM / 128, BATCH / 128), 256, SMS>>>(
            ph116, HDIM, HDIM, ph116, HDIM, paw2, ab2,
            ans_out + (size_t)s * BATCH * ODIM, pans16, ODIM, HDIM);
    }
}

// round 8
// speedup vs baseline: 2.7591x; 1.0070x over previous
#include <cuda_runtime.h>
#include <cuda_fp16.h>
#include <cstdint>
#include <math.h>

#define BATCH   4096
#define IDIM    1024
#define LDIM    1024
#define HDIM    2048
#define ODIM    512
#define HALTH   1024
#define OUTER   8
#define INNER   4

// ---------------------------------------------------------------------------
// Device-global scratch (no allocation allowed)
// ---------------------------------------------------------------------------
__device__ float  g_stateA[BATCH * LDIM];      // fp32 GRU state (ping)
__device__ float  g_stateB[BATCH * LDIM];      // fp32 GRU state (pong)
__device__ float  g_xgbase[BATCH * 3 * LDIM];  // inputs @ W_ih_in^T + b_ih (fp32)

__device__ __half g_xg16[BATCH * 3 * LDIM];    // full x_gates per outer step
__device__ __half g_h216[BATCH * HALTH];

__device__ __half g_state16A[BATCH * LDIM];    // fp16 state (ping)
__device__ __half g_state16B[BATCH * LDIM];    // fp16 state (pong)
__device__ __half g_ans16[BATCH * ODIM];
__device__ __half g_in16[BATCH * IDIM];
__device__ __half g_h116[BATCH * HDIM];

__device__ __half g_wih16[3 * LDIM * (IDIM + ODIM)];
__device__ __half g_whh16[3 * LDIM * LDIM];
__device__ __half g_aw116[HDIM * (LDIM + ODIM)];
__device__ __half g_aw216[ODIM * HDIM];
__device__ __half g_hw116[HALTH * (LDIM + ODIM)];

__device__ __forceinline__ uint32_t smem_u32(const void* p) {
    uint32_t a;
    asm("{ .reg .u64 t; cvta.to.shared.u64 t, %1; cvt.u32.u64 %0, t; }" : "=r"(a) : "l"(p));
    return a;
}

// Swizzled smem layout: rows of 32 halves (64B) packed into 128B lines.
// Conflict-free for cp.async fill and ldmatrix reads (validated rounds 4-6).
__device__ __forceinline__ uint32_t soff(int r, int c) {
    return (uint32_t)((((r >> 1) * 8) + ((((r & 1) << 2) | c) ^ ((r >> 1) & 7))) << 4);
}

// ---------------------------------------------------------------------------
// Generic fp16 tensor-core GEMM:  C = act( concat(A1,A2) @ W^T + bias|C0 )
// ---------------------------------------------------------------------------
template <int WM, int WN, int MI, int NG, int W32, int W16, int ACT, int ADDC>
__global__ void __launch_bounds__(WM * WN * 32)
hgemm(const __half* __restrict__ A1, int lda1, int K1,
      const __half* __restrict__ A2, int lda2,
      const __half* __restrict__ W, int ldw,
      const float* __restrict__ bias,
      const float* __restrict__ C0,   // fp32 addend matrix (ADDC)
      float* __restrict__ C,
      __half* __restrict__ C2,
      int N, int K)
{
    constexpr int THREADS = WM * WN * 32;
    constexpr int BM      = WM * MI * 16;
    constexpr int BN      = WN * NG * 16;
    constexpr int NI      = 2 * NG;
    constexpr int STAGE   = (BM + BN) * 64;
    constexpr int NLOAD   = (BM + BN) * 4 / THREADS;

    extern __shared__ __align__(128) char smem[];
    const uint32_t sb = smem_u32(smem);

    const int tid  = threadIdx.x;
    const int lane = tid & 31;
    const int warp = tid >> 5;
    const int wm   = warp / WN;
    const int wn   = warp % WN;
    const int row0 = blockIdx.y * BM;
    const int col0 = blockIdx.x * BN;

    float c[MI][NI][4];
#pragma unroll
    for (int i = 0; i < MI; i++)
#pragma unroll
        for (int j = 0; j < NI; j++)
#pragma unroll
            for (int k = 0; k < 4; k++) c[i][j][k] = 0.0f;

    const int nc = K >> 5;

    auto load_chunk = [&](int t) {
        const int st = t % 3;
        const int k0 = t << 5;
        const __half* Ab;
        int lda;
        if (k0 < K1) { Ab = A1 + k0;        lda = lda1; }
        else         { Ab = A2 + (k0 - K1); lda = lda2; }
        const uint32_t aB = sb + st * STAGE;
        const uint32_t bB = aB + BM * 64;
#pragma unroll
        for (int j = 0; j < NLOAD; j++) {
            const int idx = j * THREADS + tid;
            if (idx < BM * 4) {
                const int r = idx >> 2, cc = idx & 3;
                const uint32_t d = aB + soff(r, cc);
                const __half* g = Ab + (size_t)(row0 + r) * lda + cc * 8;
                asm volatile("cp.async.cg.shared.global [%0], [%1], 16;" :: "r"(d), "l"(g));
            } else {
                const int li = idx - BM * 4;
                const int r = li >> 2, cc = li & 3;
                const uint32_t d = bB + soff(r, cc);
                const __half* g = W + (size_t)(col0 + r) * ldw + k0 + cc * 8;
                asm volatile("cp.async.cg.shared.global [%0], [%1], 16;" :: "r"(d), "l"(g));
            }
        }
        asm volatile("cp.async.commit_group;");
    };

    load_chunk(0);
    load_chunk(1);

    for (int t = 0; t < nc; t++) {
        if (t + 2 <= nc) asm volatile("cp.async.wait_group 1;");
        else             asm volatile("cp.async.wait_group 0;");
        __syncthreads();
        if (t + 2 < nc) load_chunk(t + 2);

        const uint32_t aB = sb + (t % 3) * STAGE;
        const uint32_t bB = aB + BM * 64;

#pragma unroll
        for (int kh = 0; kh < 2; kh++) {
            uint32_t a[MI][4];
#pragma unroll
            for (int mi = 0; mi < MI; mi++) {
                const int row = wm * (16 * MI) + mi * 16 + (lane & 15);
                const int cc  = kh * 2 + (lane >> 4);
                asm volatile("ldmatrix.sync.aligned.m8n8.x4.shared.b16 {%0,%1,%2,%3}, [%4];"
                             : "=r"(a[mi][0]), "=r"(a[mi][1]), "=r"(a[mi][2]), "=r"(a[mi][3])
                             : "r"(aB + soff(row, cc)));
            }
            uint32_t b[NG][4];
#pragma unroll
            for (int ng = 0; ng < NG; ng++) {
                const int row = wn * (16 * NG) + ng * 16 + (lane & 7) + ((lane >> 4) << 3);
                const int cc  = kh * 2 + ((lane >> 3) & 1);
                asm volatile("ldmatrix.sync.aligned.m8n8.x4.shared.b16 {%0,%1,%2,%3}, [%4];"
                             : "=r"(b[ng][0]), "=r"(b[ng][1]), "=r"(b[ng][2]), "=r"(b[ng][3])
                             : "r"(bB + soff(row, cc)));
            }
#pragma unroll
            for (int mi = 0; mi < MI; mi++)
#pragma unroll
                for (int ng = 0; ng < NG; ng++) {
                    asm volatile(
                        "mma.sync.aligned.m16n8k16.row.col.f32.f16.f16.f32 "
                        "{%0,%1,%2,%3},{%4,%5,%6,%7},{%8,%9},{%0,%1,%2,%3};"
                        : "+f"(c[mi][2 * ng][0]), "+f"(c[mi][2 * ng][1]),
                          "+f"(c[mi][2 * ng][2]), "+f"(c[mi][2 * ng][3])
                        : "r"(a[mi][0]), "r"(a[mi][1]), "r"(a[mi][2]), "r"(a[mi][3]),
                          "r"(b[ng][0]), "r"(b[ng][1]));
                    asm volatile(
                        "mma.sync.aligned.m16n8k16.row.col.f32.f16.f16.f32 "
                        "{%0,%1,%2,%3},{%4,%5,%6,%7},{%8,%9},{%0,%1,%2,%3};"
                        : "+f"(c[mi][2 * ng + 1][0]), "+f"(c[mi][2 * ng + 1][1]),
                          "+f"(c[mi][2 * ng + 1][2]), "+f"(c[mi][2 * ng + 1][3])
                        : "r"(a[mi][0]), "r"(a[mi][1]), "r"(a[mi][2]), "r"(a[mi][3]),
                          "r"(b[ng][2]), "r"(b[ng][3]));
                }
        }
    }

    // Epilogue
#pragma unroll
    for (int mi = 0; mi < MI; mi++) {
        const int r0 = row0 + wm * (16 * MI) + mi * 16 + (lane >> 2);
#pragma unroll
        for (int ni = 0; ni < NI; ni++) {
            const int col = col0 + wn * (16 * NG) + ni * 8 + (lane & 3) * 2;
            const size_t i0 = (size_t)r0 * N + col;
            const size_t i1 = (size_t)(r0 + 8) * N + col;
            float v00, v01, v10, v11;
            if (ADDC) {
                const float2 a0 = *(const float2*)&C0[i0];
                const float2 a1 = *(const float2*)&C0[i1];
                v00 = c[mi][ni][0] + a0.x; v01 = c[mi][ni][1] + a0.y;
                v10 = c[mi][ni][2] + a1.x; v11 = c[mi][ni][3] + a1.y;
            } else {
                const float b0 = __ldg(&bias[col]);
                const float b1 = __ldg(&bias[col + 1]);
                v00 = c[mi][ni][0] + b0; v01 = c[mi][ni][1] + b1;
                v10 = c[mi][ni][2] + b0; v11 = c[mi][ni][3] + b1;
            }
            if (ACT == 1) {
                v00 = fmaxf(v00, 0.0f); v01 = fmaxf(v01, 0.0f);
                v10 = fmaxf(v10, 0.0f); v11 = fmaxf(v11, 0.0f);
            }
            if (W32) {
                C[i0] = v00; C[i0 + 1] = v01;
                C[i1] = v10; C[i1 + 1] = v11;
            }
            if (W16) {
                float w00 = v00, w01 = v01, w10 = v10, w11 = v11;
                if (ACT == 2) {
                    w00 = tanhf(v00); w01 = tanhf(v01);
                    w10 = tanhf(v10); w11 = tanhf(v11);
                }
                *(__half2*)&C2[i0] = __floats2half2_rn(w00, w01);
                *(__half2*)&C2[i1] = __floats2half2_rn(w10, w11);
            }
        }
    }
}

// ---------------------------------------------------------------------------
// Fused GRU GEMM with DOUBLE-BUFFERED state (fixes round-7 cross-CTA race):
// h_gates = s16in @ W_hh^T (+b_hh), GRU update in epilogue, writes s*out.
// Gate interleave: B-tile row rb -> weight row gate*L + j, so accumulators
// (p, 2+p, 4+p) hold (r,z,n) of the same j. BM=128, BN=192, 512 threads.
// ---------------------------------------------------------------------------
__global__ void __launch_bounds__(512)
gru_gemm(const float* __restrict__ bhh,
         const __half* __restrict__ s16in,
         const float* __restrict__ s32in,
         __half* __restrict__ s16out,
         float* __restrict__ s32out)
{
    constexpr int STAGE = (128 + 192) * 64;   // 20480 B

    extern __shared__ __align__(128) char smem[];
    const uint32_t sb = smem_u32(smem);

    const int tid  = threadIdx.x;
    const int lane = tid & 31;
    const int warp = tid >> 5;
    const int wm   = warp >> 2;   // 0..3
    const int wn   = warp & 3;    // 0..3
    const int row0 = blockIdx.y * 128;
    const int c0j  = blockIdx.x * 64;  // j-range base

    float c[2][6][4];
#pragma unroll
    for (int i = 0; i < 2; i++)
#pragma unroll
        for (int j = 0; j < 6; j++)
#pragma unroll
            for (int k = 0; k < 4; k++) c[i][j][k] = 0.0f;

    auto load_chunk = [&](int t) {
        const int st = t % 3;
        const int k0 = t << 5;
        const uint32_t aB = sb + st * STAGE;
        const uint32_t bB = aB + 128 * 64;
#pragma unroll
        for (int j = 0; j < 3; j++) {
            const int idx = j * 512 + tid;
            if (idx < 512) {                       // A: 128 rows x 4 chunks
                const int r = idx >> 2, cc = idx & 3;
                const uint32_t d = aB + soff(r, cc);
                const __half* g = s16in + (size_t)(row0 + r) * LDIM + k0 + cc * 8;
                asm volatile("cp.async.cg.shared.global [%0], [%1], 16;" :: "r"(d), "l"(g));
            } else if (idx < 512 + 768) {          // B: 192 rows x 4 chunks
                const int li = idx - 512;
                const int rb = li >> 2, cc = li & 3;
                const int within = rb % 48;
                const int wrow = (within >> 4) * LDIM + c0j + (rb / 48) * 16 + (within & 15);
                const uint32_t d = bB + soff(rb, cc);
                const __half* g = g_whh16 + (size_t)wrow * LDIM + k0 + cc * 8;
                asm volatile("cp.async.cg.shared.global [%0], [%1], 16;" :: "r"(d), "l"(g));
            }
        }
        asm volatile("cp.async.commit_group;");
    };

    load_chunk(0);
    load_chunk(1);

    const int nc = LDIM >> 5;  // 32
    for (int t = 0; t < nc; t++) {
        if (t + 2 <= nc) asm volatile("cp.async.wait_group 1;");
        else             asm volatile("cp.async.wait_group 0;");
        __syncthreads();
        if (t + 2 < nc) load_chunk(t + 2);

        const uint32_t aB = sb + (t % 3) * STAGE;
        const uint32_t bB = aB + 128 * 64;

#pragma unroll
        for (int kh = 0; kh < 2; kh++) {
            uint32_t a[2][4];
#pragma unroll
            for (int mi = 0; mi < 2; mi++) {
                const int row = wm * 32 + mi * 16 + (lane & 15);
                const int cc  = kh * 2 + (lane >> 4);
                asm volatile("ldmatrix.sync.aligned.m8n8.x4.shared.b16 {%0,%1,%2,%3}, [%4];"
                             : "=r"(a[mi][0]), "=r"(a[mi][1]), "=r"(a[mi][2]), "=r"(a[mi][3])
                             : "r"(aB + soff(row, cc)));
            }
            uint32_t b[3][4];
#pragma unroll
            for (int ng = 0; ng < 3; ng++) {
                const int row = wn * 48 + ng * 16 + (lane & 7) + ((lane >> 4) << 3);
                const int cc  = kh * 2 + ((lane >> 3) & 1);
                asm volatile("ldmatrix.sync.aligned.m8n8.x4.shared.b16 {%0,%1,%2,%3}, [%4];"
                             : "=r"(b[ng][0]), "=r"(b[ng][1]), "=r"(b[ng][2]), "=r"(b[ng][3])
                             : "r"(bB + soff(row, cc)));
            }
#pragma unroll
            for (int mi = 0; mi < 2; mi++)
#pragma unroll
                for (int ng = 0; ng < 3; ng++) {
                    asm volatile(
                        "mma.sync.aligned.m16n8k16.row.col.f32.f16.f16.f32 "
                        "{%0,%1,%2,%3},{%4,%5,%6,%7},{%8,%9},{%0,%1,%2,%3};"
                        : "+f"(c[mi][2 * ng][0]), "+f"(c[mi][2 * ng][1]),
                          "+f"(c[mi][2 * ng][2]), "+f"(c[mi][2 * ng][3])
                        : "r"(a[mi][0]), "r"(a[mi][1]), "r"(a[mi][2]), "r"(a[mi][3]),
                          "r"(b[ng][0]), "r"(b[ng][1]));
                    asm volatile(
                        "mma.sync.aligned.m16n8k16.row.col.f32.f16.f16.f32 "
                        "{%0,%1,%2,%3},{%4,%5,%6,%7},{%8,%9},{%0,%1,%2,%3};"
                        : "+f"(c[mi][2 * ng + 1][0]), "+f"(c[mi][2 * ng + 1][1]),
                          "+f"(c[mi][2 * ng + 1][2]), "+f"(c[mi][2 * ng + 1][3])
                        : "r"(a[mi][0]), "r"(a[mi][1]), "r"(a[mi][2]), "r"(a[mi][3]),
                          "r"(b[ng][2]), "r"(b[ng][3]));
                }
        }
    }

    // Fused GRU epilogue: warp-tile cols = [r 0..15 | z 16..31 | n 32..47]
#pragma unroll
    for (int mi = 0; mi < 2; mi++) {
        const int r0 = row0 + wm * 32 + mi * 16 + (lane >> 2);
#pragma unroll
        for (int p = 0; p < 2; p++) {
            const int j0 = c0j + wn * 16 + p * 8 + (lane & 3) * 2;
            const float2 br = *(const float2*)&bhh[j0];
            const float2 bz = *(const float2*)&bhh[LDIM + j0];
            const float2 bn = *(const float2*)&bhh[2 * LDIM + j0];
            const float* cr = c[mi][p];
            const float* cz = c[mi][2 + p];
            const float* cn = c[mi][4 + p];
#pragma unroll
            for (int h = 0; h < 2; h++) {
                const int row = r0 + h * 8;
                const float hr0 = cr[2 * h] + br.x, hr1 = cr[2 * h + 1] + br.y;
                const float hz0 = cz[2 * h] + bz.x, hz1 = cz[2 * h + 1] + bz.y;
                const float hn0 = cn[2 * h] + bn.x, hn1 = cn[2 * h + 1] + bn.y;
                const size_t xb = (size_t)row * (3 * LDIM) + j0;
                const float2 xr = __half22float2(*(const __half2*)&g_xg16[xb]);
                const float2 xz = __half22float2(*(const __half2*)&g_xg16[xb + LDIM]);
                const float2 xn = __half22float2(*(const __half2*)&g_xg16[xb + 2 * LDIM]);
                const size_t si = (size_t)row * LDIM + j0;
                const float2 s = *(const float2*)&s32in[si];

                const float rr0 = 1.0f / (1.0f + expf(-(xr.x + hr0)));
                const float zz0 = 1.0f / (1.0f + expf(-(xz.x + hz0)));
                const float nn0 = tanhf(xn.x + rr0 * hn0);
                const float rr1 = 1.0f / (1.0f + expf(-(xr.y + hr1)));
                const float zz1 = 1.0f / (1.0f + expf(-(xz.y + hz1)));
                const float nn1 = tanhf(xn.y + rr1 * hn1);

                float2 ns;
                ns.x = (1.0f - zz0) * nn0 + zz0 * s.x;
                ns.y = (1.0f - zz1) * nn1 + zz1 * s.y;
                *(float2*)&s32out[si] = ns;
                *(__half2*)&s16out[si] = __floats2half2_rn(ns.x, ns.y);
            }
        }
    }
}

// ---------------------------------------------------------------------------
// Elementwise / small kernels
// ---------------------------------------------------------------------------
__global__ void cvt16(const float* __restrict__ src, __half* __restrict__ dst) {
    const int i = blockIdx.x * blockDim.x + threadIdx.x;
    dst[i] = __float2half_rn(src[i]);
}

__global__ void halt_kernel(const float* __restrict__ hw2,
                            const float* __restrict__ hb2,
                            float* __restrict__ out) {
    const int row  = blockIdx.x * (blockDim.x >> 5) + (threadIdx.x >> 5);
    const int lane = threadIdx.x & 31;
    const __half2* h = (const __half2*)(g_h216 + (size_t)row * HALTH);
    const float2* w0 = (const float2*)hw2;
    const float2* w1 = (const float2*)(hw2 + HALTH);
    float s0 = 0.0f, s1 = 0.0f;
    for (int k = lane; k < HALTH / 2; k += 32) {
        const float2 v  = __half22float2(h[k]);
        const float2 a0 = w0[k];
        const float2 a1 = w1[k];
        s0 += v.x * a0.x + v.y * a0.y;
        s1 += v.x * a1.x + v.y * a1.y;
    }
#pragma unroll
    for (int o = 16; o > 0; o >>= 1) {
        s0 += __shfl_down_sync(0xFFFFFFFFu, s0, o);
        s1 += __shfl_down_sync(0xFFFFFFFFu, s1, o);
    }
    if (lane == 0) {
        out[(size_t)row * 2]     = s0 + hb2[0];
        out[(size_t)row * 2 + 1] = s1 + hb2[1];
    }
}

// ---------------------------------------------------------------------------
// Host orchestration
// ---------------------------------------------------------------------------
extern "C" void kernel_launch(void* const* d_in, const int* in_sizes, int n_in,
                              void* d_out, int out_size)
{
    const float* inputs = (const float*)d_in[0];
    const float* W_ih   = (const float*)d_in[1];
    const float* W_hh   = (const float*)d_in[2];
    const float* b_ih   = (const float*)d_in[3];
    const float* b_hh   = (const float*)d_in[4];
    const float* aw1    = (const float*)d_in[5];
    const float* ab1    = (const float*)d_in[6];
    const float* aw2    = (const float*)d_in[7];
    const float* ab2    = (const float*)d_in[8];
    const float* hw1    = (const float*)d_in[9];
    const float* hb1    = (const float*)d_in[10];
    const float* hw2    = (const float*)d_in[11];
    const float* hb2    = (const float*)d_in[12];

    float* out = (float*)d_out;
    float* ans_out  = out;                                  // [8, 4096, 512]
    float* halt_out = out + (size_t)OUTER * BATCH * ODIM;   // [8, 4096, 2]

    float *psA, *psB, *pxgbase;
    __half *ps16A, *ps16B, *pxg, *ph216, *pans16, *pin16, *ph116;
    __half *pwih, *pwhh, *paw1, *paw2, *phw1;
    cudaGetSymbolAddress((void**)&psA,     g_stateA);
    cudaGetSymbolAddress((void**)&psB,     g_stateB);
    cudaGetSymbolAddress((void**)&pxgbase, g_xgbase);
    cudaGetSymbolAddress((void**)&pxg,     g_xg16);
    cudaGetSymbolAddress((void**)&ph216,   g_h216);
    cudaGetSymbolAddress((void**)&ps16A,   g_state16A);
    cudaGetSymbolAddress((void**)&ps16B,   g_state16B);
    cudaGetSymbolAddress((void**)&pans16,  g_ans16);
    cudaGetSymbolAddress((void**)&pin16,   g_in16);
    cudaGetSymbolAddress((void**)&ph116,   g_h116);
    cudaGetSymbolAddress((void**)&pwih,    g_wih16);
    cudaGetSymbolAddress((void**)&pwhh,    g_whh16);
    cudaGetSymbolAddress((void**)&paw1,    g_aw116);
    cudaGetSymbolAddress((void**)&paw2,    g_aw216);
    cudaGetSymbolAddress((void**)&phw1,    g_hw116);

    const int SMB = 3 * (256 + 128) * 64;  // 73728 (BM=256 configs)
    const int SMS = 3 * (128 + 128) * 64;  // 49152 (logits)
    const int SMG = 3 * (128 + 192) * 64;  // 61440 (fused GRU GEMM)
    cudaFuncSetAttribute(hgemm<4, 4, 4, 2, 1, 0, 0, 0>, cudaFuncAttributeMaxDynamicSharedMemorySize, SMB);
    cudaFuncSetAttribute(hgemm<4, 4, 4, 2, 0, 1, 0, 1>, cudaFuncAttributeMaxDynamicSharedMemorySize, SMB);
    cudaFuncSetAttribute(hgemm<4, 4, 4, 2, 0, 1, 1, 0>, cudaFuncAttributeMaxDynamicSharedMemorySize, SMB);
    cudaFuncSetAttribute(hgemm<4, 2, 2, 4, 1, 1, 2, 0>, cudaFuncAttributeMaxDynamicSharedMemorySize, SMS);
    cudaFuncSetAttribute(gru_gemm, cudaFuncAttributeMaxDynamicSharedMemorySize, SMG);

    cudaMemsetAsync(psA,   0, sizeof(float)  * BATCH * LDIM);
    cudaMemsetAsync(ps16A, 0, sizeof(__half) * BATCH * LDIM);
    cudaMemsetAsync(pans16, 0, sizeof(__half) * BATCH * ODIM);

    // One-time fp16 conversions
    cvt16<<<(BATCH * IDIM) / 256, 256>>>(inputs, pin16);
    cvt16<<<(3 * LDIM * (IDIM + ODIM)) / 256, 256>>>(W_ih, pwih);
    cvt16<<<(3 * LDIM * LDIM) / 256, 256>>>(W_hh, pwhh);
    cvt16<<<(HDIM * (LDIM + ODIM)) / 256, 256>>>(aw1, paw1);
    cvt16<<<(ODIM * HDIM) / 256, 256>>>(aw2, paw2);
    cvt16<<<(HALTH * (LDIM + ODIM)) / 256, 256>>>(hw1, phw1);

    // xg_base = inputs @ W_ih[:, :IDIM]^T + b_ih   (fp32, once)
    hgemm<4, 4, 4, 2, 1, 0, 0, 0><<<dim3((3 * LDIM) / 128, BATCH / 256), 512, SMB>>>(
        pin16, IDIM, IDIM, pin16, IDIM, pwih, IDIM + ODIM, b_ih, nullptr,
        pxgbase, nullptr, 3 * LDIM, IDIM);

    for (int s = 0; s < OUTER; s++) {
        // xg = xg_base + ans @ W_ih[:, IDIM:]^T     [B, 3L] fp16
        hgemm<4, 4, 4, 2, 0, 1, 0, 1><<<dim3((3 * LDIM) / 128, BATCH / 256), 512, SMB>>>(
            pans16, ODIM, ODIM, pans16, ODIM, pwih + IDIM, IDIM + ODIM, nullptr, pxgbase,
            nullptr, pxg, 3 * LDIM, ODIM);

        // 4x fused GRU GEMM, ping-pong state A->B->A->B->A (ends in A)
        for (int i = 0; i < INNER; i++) {
            const bool even = (i & 1) == 0;
            gru_gemm<<<dim3(LDIM / 64, BATCH / 128), 512, SMG>>>(
                b_hh,
                even ? ps16A : ps16B, even ? psA : psB,
                even ? ps16B : ps16A, even ? psB : psA);
        }

        // h1 = relu(concat(state, ans) @ aw1^T + ab1)   [B, H] fp16
        hgemm<4, 4, 4, 2, 0, 1, 1, 0><<<dim3(HDIM / 128, BATCH / 256), 512, SMB>>>(
            ps16A, LDIM, LDIM, pans16, ODIM, paw1, LDIM + ODIM, ab1, nullptr,
            nullptr, ph116, HDIM, LDIM + ODIM);

        // h2 = relu(concat(state, ans) @ hw1^T + hb1)   [B, HALT_H] fp16
        hgemm<4, 4, 4, 2, 0, 1, 1, 0><<<dim3(HALTH / 128, BATCH / 256), 512, SMB>>>(
            ps16A, LDIM, LDIM, pans16, ODIM, phw1, LDIM + ODIM, hb1, nullptr,
            nullptr, ph216, HALTH, LDIM + ODIM);

        // halt = h2 @ hw2^T + hb2                        [B, 2]
        halt_kernel<<<BATCH / 8, 256>>>(hw2, hb2, halt_out + (size_t)s * BATCH * 2);

        // logits -> out (fp32); ans16 = half(tanh(logits))
        hgemm<4, 2, 2, 4, 1, 1, 2, 0><<<dim3(ODIM / 128, BATCH / 128), 256, SMS>>>(
            ph116, HDIM, HDIM, ph116, HDIM, paw2, HDIM, ab2, nullptr,
            ans_out + (size_t)s * BATCH * ODIM, pans16, ODIM, HDIM);
    }
}